// round 1
// baseline (speedup 1.0000x reference)
#include <cuda_runtime.h>
#include <cuda_bf16.h>

// RNN: h_t = tanh(h_{t-1} + x_t @ W1 + b1), out = sigmoid(h_63 @ W2 + b2)
// x: [B, 64, 16] f32, W1: [16,10], b1: [10], W2: [10,5], b2: [5], out: [B,5] f32
//
// Design: one warp per 32 batches. Per timestep, the warp cooperatively loads
// 32 batches x 16 floats (coalesced float4) into a bank-conflict-free smem
// staging buffer (row stride 33 floats), then each lane runs its own batch's
// recurrence with W1/b1 packed into f32x2 registers and FFMA2 (fma.rn.f32x2).
// Loads are pipelined 2 steps ahead in registers to hide DRAM latency.

#define SEQ   64
#define INF   16
#define HID   10
#define OUTF  5
#define ROWF  (SEQ*INF)   // 1024 floats per batch
#define STRIDE 33         // smem row stride (odd -> conflict-free lane reads)

typedef unsigned long long u64;

__device__ __forceinline__ u64 pack2(float lo, float hi) {
    u64 r; asm("mov.b64 %0, {%1,%2};" : "=l"(r) : "f"(lo), "f"(hi)); return r;
}
__device__ __forceinline__ void unpack2(float& lo, float& hi, u64 v) {
    asm("mov.b64 {%0,%1}, %2;" : "=f"(lo), "=f"(hi) : "l"(v));
}
__device__ __forceinline__ u64 fma2(u64 a, u64 b, u64 c) {
    u64 d; asm("fma.rn.f32x2 %0, %1, %2, %3;" : "=l"(d) : "l"(a), "l"(b), "l"(c)); return d;
}
__device__ __forceinline__ u64 add2(u64 a, u64 b) {
    u64 d; asm("add.rn.f32x2 %0, %1, %2;" : "=l"(d) : "l"(a), "l"(b)); return d;
}
// tanh(x) = 2/(1+exp(-2x)) - 1 ; ex2/rcp approx give ~1e-7 abs error
__device__ __forceinline__ float tanh_fast(float x) {
    float e; asm("ex2.approx.f32 %0, %1;" : "=f"(e) : "f"(x * -2.8853900817779268f));
    float r; asm("rcp.approx.f32 %0, %1;" : "=f"(r) : "f"(e + 1.0f));
    return fmaf(2.0f, r, -1.0f);
}
__device__ __forceinline__ float sigmoid_fast(float x) {
    float e; asm("ex2.approx.f32 %0, %1;" : "=f"(e) : "f"(x * -1.4426950408889634f));
    float r; asm("rcp.approx.f32 %0, %1;" : "=f"(r) : "f"(e + 1.0f));
    return r;
}

__global__ void __launch_bounds__(128, 2)
rnn_kernel(const float* __restrict__ x,
           const float* __restrict__ W1,
           const float* __restrict__ b1,
           const float* __restrict__ W2,
           const float* __restrict__ b2,
           float* __restrict__ out,
           int nbatch)
{
    __shared__ float buf[4][32 * STRIDE];   // per-warp staging, 2 timestep halves

    const int lane = threadIdx.x & 31;
    const int wid  = threadIdx.x >> 5;
    const long wbase = ((long)blockIdx.x * 4 + wid) * 32;
    if (wbase >= nbatch) return;

    const float* xw = x + wbase * ROWF;
    float* sb = buf[wid];

    // ---- pack weights into registers (broadcast loads, one-time) ----
    u64 W1p[80];   // W1p[i*5+jp] = (W1[i][2jp], W1[i][2jp+1])
    u64 b1p[5], h[5];
#pragma unroll
    for (int i = 0; i < 16; ++i)
#pragma unroll
        for (int jp = 0; jp < 5; ++jp)
            W1p[i*5 + jp] = __ldg(reinterpret_cast<const u64*>(W1) + i*5 + jp);
#pragma unroll
    for (int jp = 0; jp < 5; ++jp) {
        b1p[jp] = __ldg(reinterpret_cast<const u64*>(b1) + jp);
        h[jp]   = 0ull;  // (0.0f, 0.0f)
    }

    // ---- pipelined load / store helpers ----
    // one timestep = 32 batches x 4 float4 = 128 float4; 4 per thread
    float4 v[4];
    auto LD = [&](int s) {
#pragma unroll
        for (int j = 0; j < 4; ++j) {
            int g  = j*32 + lane;
            int bl = g >> 2;        // batch-local 0..31
            int w  = g & 3;         // float4 index 0..3 within step
            v[j] = __ldcs(reinterpret_cast<const float4*>(xw + bl*ROWF + s*INF + w*4));
        }
    };
    auto ST = [&](int s) {
#pragma unroll
        for (int j = 0; j < 4; ++j) {
            int g  = j*32 + lane;
            int bl = g >> 2;
            int w  = g & 3;
            float* d = sb + bl*STRIDE + (s & 1)*16 + w*4;
            d[0] = v[j].x; d[1] = v[j].y; d[2] = v[j].z; d[3] = v[j].w;
        }
    };

    LD(0); ST(0); LD(1);
    __syncwarp();

    const float* myrow = sb + lane*STRIDE;

#pragma unroll 2
    for (int s = 0; s < SEQ; ++s) {
        // ---- recurrence step s (data in smem half s&1) ----
        u64 acc[5];
#pragma unroll
        for (int jp = 0; jp < 5; ++jp) acc[jp] = add2(h[jp], b1p[jp]);

#pragma unroll
        for (int i = 0; i < 16; ++i) {
            float xi = myrow[(s & 1)*16 + i];
            u64 xx = pack2(xi, xi);
#pragma unroll
            for (int jp = 0; jp < 5; ++jp)
                acc[jp] = fma2(xx, W1p[i*5 + jp], acc[jp]);
        }
#pragma unroll
        for (int jp = 0; jp < 5; ++jp) {
            float lo, hi; unpack2(lo, hi, acc[jp]);
            lo = tanh_fast(lo);
            hi = tanh_fast(hi);
            h[jp] = pack2(lo, hi);
        }

        // ---- feed the pipeline: store step s+1 (already in regs), load s+2 ----
        if (s < SEQ-1) {
            ST(s+1);
            if (s < SEQ-2) LD(s+2);
        }
        __syncwarp();
    }

    // ---- epilogue: out = sigmoid(h @ W2 + b2) ----
    float hh[10];
#pragma unroll
    for (int jp = 0; jp < 5; ++jp) unpack2(hh[2*jp], hh[2*jp+1], h[jp]);

    const long b = wbase + lane;
    if (b < nbatch) {
#pragma unroll
        for (int o = 0; o < OUTF; ++o) {
            float a = __ldg(b2 + o);
#pragma unroll
            for (int j = 0; j < HID; ++j)
                a = fmaf(hh[j], __ldg(W2 + j*OUTF + o), a);
            out[b*OUTF + o] = sigmoid_fast(a);
        }
    }
}

extern "C" void kernel_launch(void* const* d_in, const int* in_sizes, int n_in,
                              void* d_out, int out_size)
{
    const float* x  = (const float*)d_in[0];
    const float* W1 = (const float*)d_in[1];
    const float* b1 = (const float*)d_in[2];
    const float* W2 = (const float*)d_in[3];
    const float* b2 = (const float*)d_in[4];
    float* out = (float*)d_out;

    int nbatch = in_sizes[0] / ROWF;           // 65536
    int nwarps = (nbatch + 31) / 32;           // 2048
    int blocks = (nwarps + 3) / 4;             // 512 blocks of 128 threads
    rnn_kernel<<<blocks, 128>>>(x, W1, b1, W2, b2, out, nbatch);
}